// round 14
// baseline (speedup 1.0000x reference)
#include <cuda_runtime.h>
#include <cuda_fp16.h>
#include <cstdint>

#define Nn 8192
#define IN_F 256
#define OUT_F 128
#define ALPHA 0.2f
#define SPLIT 4
#define JQ (Nn / SPLIT)    /* 2048 cols per CTA */
#define NIT (JQ / 16)      /* 128 k16 iterations */

// ---------------- scratch (device globals; no allocation allowed) ------------
__device__ float g_f1[Nn];
__device__ float g_f2[Nn];
__device__ float g_f2pmax[256];
__device__ __align__(16) float2 g_tab2[Nn];   // (exp(f2-fm), exp(a*(f2-fm)))
__device__ __align__(16) float2 g_rowc[Nn];   // (cp, cn)
// Wh in fp16, MMA-fragment-major, uint4-paired n-tiles (see k_proj writer)
__device__ __align__(16) uint4 g_Bf[(Nn / 16) * 8 * 32];
__device__ float g_np[SPLIT][Nn * OUT_F];   // partial numerators per j-quarter
__device__ float g_lp[SPLIT][Nn];           // partial row sums

// ---------------- helpers ----------------------------------------------------
__device__ __forceinline__ void mma_f16(float* d, const uint32_t* a, uint32_t b0, uint32_t b1) {
    asm volatile("mma.sync.aligned.m16n8k16.row.col.f32.f16.f16.f32 "
                 "{%0,%1,%2,%3},{%4,%5,%6,%7},{%8,%9},{%0,%1,%2,%3};"
                 : "+f"(d[0]), "+f"(d[1]), "+f"(d[2]), "+f"(d[3])
                 : "r"(a[0]), "r"(a[1]), "r"(a[2]), "r"(a[3]), "r"(b0), "r"(b1));
}

__device__ __forceinline__ uint32_t packh2(float hi, float lo) {
    uint32_t r;
    asm("cvt.rn.f16x2.f32 %0, %1, %2;" : "=r"(r) : "f"(hi), "f"(lo));
    return r;
}

// ---------------------------------------------------------------------------
// Kernel 1: Wh = h@W ; f1/f2, per-block f2 max, fragment-major fp16 Bf.
// ---------------------------------------------------------------------------
__global__ __launch_bounds__(256) void k_proj(const float* __restrict__ h,
                                              const float* __restrict__ W,
                                              const float* __restrict__ a) {
    __shared__ float w_s[32 * 128];
    __shared__ float h_s[32 * 33];
    __shared__ float red[32];
    const int tid = threadIdx.x;
    const int i0 = blockIdx.x * 32;
    const int row = tid >> 3;
    const int c8 = tid & 7;
    float4 acc[4];
#pragma unroll
    for (int j4 = 0; j4 < 4; j4++) acc[j4] = make_float4(0.f, 0.f, 0.f, 0.f);

    for (int kc = 0; kc < IN_F; kc += 32) {
        __syncthreads();
        const float4* wsrc = (const float4*)(W + kc * OUT_F);
#pragma unroll
        for (int u = 0; u < 4; u++) ((float4*)w_s)[tid + u * 256] = wsrc[tid + u * 256];
        {
            float4 hv = *(const float4*)(h + (size_t)(i0 + row) * IN_F + kc + c8 * 4);
            h_s[row * 33 + c8 * 4 + 0] = hv.x;
            h_s[row * 33 + c8 * 4 + 1] = hv.y;
            h_s[row * 33 + c8 * 4 + 2] = hv.z;
            h_s[row * 33 + c8 * 4 + 3] = hv.w;
        }
        __syncthreads();
#pragma unroll
        for (int kk = 0; kk < 32; kk++) {
            const float hval = h_s[row * 33 + kk];
            const float4* wr = ((const float4*)w_s) + kk * 32 + c8;
#pragma unroll
            for (int j4 = 0; j4 < 4; j4++) {
                const float4 wv = wr[j4 * 8];
                acc[j4].x = fmaf(hval, wv.x, acc[j4].x);
                acc[j4].y = fmaf(hval, wv.y, acc[j4].y);
                acc[j4].z = fmaf(hval, wv.z, acc[j4].z);
                acc[j4].w = fmaf(hval, wv.w, acc[j4].w);
            }
        }
    }

    float s1 = 0.f, s2 = 0.f;
#pragma unroll
    for (int j4 = 0; j4 < 4; j4++) {
        const float4 a1v = *(const float4*)(a + c8 * 4 + j4 * 32);
        const float4 a2v = *(const float4*)(a + OUT_F + c8 * 4 + j4 * 32);
        s1 += acc[j4].x * a1v.x + acc[j4].y * a1v.y + acc[j4].z * a1v.z + acc[j4].w * a1v.w;
        s2 += acc[j4].x * a2v.x + acc[j4].y * a2v.y + acc[j4].z * a2v.z + acc[j4].w * a2v.w;
    }
#pragma unroll
    for (int o = 1; o < 8; o <<= 1) {
        s1 += __shfl_xor_sync(0xFFFFFFFFu, s1, o);
        s2 += __shfl_xor_sync(0xFFFFFFFFu, s2, o);
    }
    if (c8 == 0) { g_f1[i0 + row] = s1; g_f2[i0 + row] = s2; red[row] = s2; }
    __syncthreads();
    if (tid < 32) {
        float m = red[tid];
#pragma unroll
        for (int o = 16; o; o >>= 1) m = fmaxf(m, __shfl_xor_sync(0xFFFFFFFFu, m, o));
        if (tid == 0) g_f2pmax[blockIdx.x] = m;
    }

    // stage Wh into w_s, then fragment-major fp16 write
#pragma unroll
    for (int j4 = 0; j4 < 4; j4++)
        ((float4*)w_s)[row * 32 + c8 + j4 * 8] = acc[j4];
    __syncthreads();

    const int f = tid & 127;
    const int hb = tid >> 7;
    const int wn = f >> 6, nt = (f >> 3) & 7, nq = f & 7;
    uint32_t* bf32 = (uint32_t*)g_Bf;
#pragma unroll
    for (int q = 0; q < 8; q++) {
        const int jj = hb * 16 + 2 * q;
        const float v0 = w_s[jj * 128 + f];
        const float v1 = w_s[(jj + 1) * 128 + f];
        const uint32_t pk = packh2(v1, v0);
        const int jblk = (i0 + jj) >> 4;
        const int cc = (jj >> 2) & 3;
        const int v = jj & 3;
        const int widx = ((((jblk * 2 + wn) * 4 + (nt >> 1)) * 32) + nq * 4 + cc) * 4
                         + (nt & 1) * 2 + (v >> 1);
        bf32[widx] = pk;
    }
}

// ---------------------------------------------------------------------------
// Kernel 2: finish f2max reduction + build col/row tables. Grid 32 x 256.
// ---------------------------------------------------------------------------
__global__ __launch_bounds__(256) void k_pre() {
    __shared__ float red[256];
    const int t = threadIdx.x;
    red[t] = g_f2pmax[t];
    __syncthreads();
#pragma unroll
    for (int s = 128; s; s >>= 1) {
        if (t < s) red[t] = fmaxf(red[t], red[t + s]);
        __syncthreads();
    }
    const float fm = red[0];
    const int j = blockIdx.x * 256 + t;
    const float d = g_f2[j] - fm;
    g_tab2[j] = make_float2(expf(d), expf(ALPHA * d));
    const float f1 = g_f1[j];
    const float bound = f1 + fm;
    const float m = bound > 0.f ? bound : ALPHA * bound;
    g_rowc[j] = make_float2(expf(bound - m), expf(ALPHA * bound - m));
}

// ---------------------------------------------------------------------------
// Kernel 3: fused masked-softmax + fp16 HMMA PV GEMM. Barrier-free main loop.
// Warp tile 16 rows x 128 feats. B: ALL 8 LDG.128 issued at iteration start
// (MLP=8); A-production covers their latency; MMAs consume afterward.
// ---------------------------------------------------------------------------
__global__ __launch_bounds__(512, 1) void k_attn(const int* __restrict__ adj) {
    __shared__ float2 tab_s[JQ];   // 16 KB

    const int tid = threadIdx.x;
    const int wid = tid >> 5, lane = tid & 31;
    const int nq = lane >> 2, c = lane & 3;
    const int rb = blockIdx.x >> 2, q = blockIdx.x & 3;
    const int i0 = rb * 256, jq = q * JQ;

    // stage the quarter's exp table into smem (once)
    {
        const float4* src = (const float4*)(g_tab2 + jq);
        float4* dst = (float4*)tab_s;
        dst[tid] = src[tid];
        dst[tid + 512] = src[tid + 512];
    }

    const int r0 = i0 + wid * 16 + nq;
    const int r1 = r0 + 8;
    const float2 rc0 = g_rowc[r0];
    const float2 rc1 = g_rowc[r1];
    const float cp0 = rc0.x, cn0 = rc0.y;
    const float cp1 = rc1.x, cn1 = rc1.y;
    const int4* arow0 = (const int4*)(adj + (size_t)r0 * Nn);
    const int4* arow1 = (const int4*)(adj + (size_t)r1 * Nn);
    const int cibase = (jq >> 2) + c;
    const uint4* bfbase = g_Bf + (size_t)(jq >> 4) * 256 + lane;

    float acc[16][4];
#pragma unroll
    for (int ng = 0; ng < 16; ng++)
#pragma unroll
        for (int u = 0; u < 4; u++) acc[ng][u] = 0.f;
    float lsum0 = 0.f, lsum1 = 0.f;

    // adj prefetch ring, distance 2
    int4 pa0[2], pa1[2];
    pa0[0] = arow0[cibase];     pa1[0] = arow1[cibase];
    pa0[1] = arow0[cibase + 4]; pa1[1] = arow1[cibase + 4];

    __syncthreads();   // tab_s ready (only barrier)

#pragma unroll 1
    for (int i = 0; i < NIT; i++) {
        // ---- issue all 8 B loads for THIS iteration first (MLP=8) ----
        const uint4* bq = bfbase + (size_t)i * 256;
        uint4 b0 = bq[0],   b1 = bq[32],  b2 = bq[64],  b3 = bq[96];
        uint4 b4 = bq[128], b5 = bq[160], b6 = bq[192], b7 = bq[224];

        const int jl = 16 * i + 4 * c;
        const int4 A0 = pa0[i & 1];
        const int4 A1 = pa1[i & 1];
        if (i + 2 < NIT) {
            pa0[i & 1] = arow0[cibase + 4 * (i + 2)];
            pa1[i & 1] = arow1[cibase + 4 * (i + 2)];
        }

        const float4 tA = *(const float4*)(tab_s + jl);      // cols j, j+1
        const float4 tB = *(const float4*)(tab_s + jl + 2);  // cols j+2, j+3

        float p00 = fmaxf(cp0 * tA.x, cn0 * tA.y);
        float p01 = fmaxf(cp0 * tA.z, cn0 * tA.w);
        float p02 = fmaxf(cp0 * tB.x, cn0 * tB.y);
        float p03 = fmaxf(cp0 * tB.z, cn0 * tB.w);
        float p10 = fmaxf(cp1 * tA.x, cn1 * tA.y);
        float p11 = fmaxf(cp1 * tA.z, cn1 * tA.w);
        float p12 = fmaxf(cp1 * tB.x, cn1 * tB.y);
        float p13 = fmaxf(cp1 * tB.z, cn1 * tB.w);
        p00 = (A0.x > 0) ? p00 : 0.f;
        p01 = (A0.y > 0) ? p01 : 0.f;
        p02 = (A0.z > 0) ? p02 : 0.f;
        p03 = (A0.w > 0) ? p03 : 0.f;
        p10 = (A1.x > 0) ? p10 : 0.f;
        p11 = (A1.y > 0) ? p11 : 0.f;
        p12 = (A1.z > 0) ? p12 : 0.f;
        p13 = (A1.w > 0) ? p13 : 0.f;
        lsum0 += (p00 + p01) + (p02 + p03);
        lsum1 += (p10 + p11) + (p12 + p13);

        uint32_t Af[4];
        Af[0] = packh2(p01, p00);   // row r0, k 2c/2c+1 (j 4c,4c+1)
        Af[1] = packh2(p11, p10);   // row r1
        Af[2] = packh2(p03, p02);   // row r0, k 2c+8/+9 (j 4c+2,4c+3)
        Af[3] = packh2(p13, p12);   // row r1

        mma_f16(acc[0],  Af, b0.x, b0.y);
        mma_f16(acc[1],  Af, b0.z, b0.w);
        mma_f16(acc[2],  Af, b1.x, b1.y);
        mma_f16(acc[3],  Af, b1.z, b1.w);
        mma_f16(acc[4],  Af, b2.x, b2.y);
        mma_f16(acc[5],  Af, b2.z, b2.w);
        mma_f16(acc[6],  Af, b3.x, b3.y);
        mma_f16(acc[7],  Af, b3.z, b3.w);
        mma_f16(acc[8],  Af, b4.x, b4.y);
        mma_f16(acc[9],  Af, b4.z, b4.w);
        mma_f16(acc[10], Af, b5.x, b5.y);
        mma_f16(acc[11], Af, b5.z, b5.w);
        mma_f16(acc[12], Af, b6.x, b6.y);
        mma_f16(acc[13], Af, b6.z, b6.w);
        mma_f16(acc[14], Af, b7.x, b7.y);
        mma_f16(acc[15], Af, b7.z, b7.w);
    }

    // row-sum reduce across the 4 c-lanes of each quad
    lsum0 += __shfl_xor_sync(0xFFFFFFFFu, lsum0, 1);
    lsum0 += __shfl_xor_sync(0xFFFFFFFFu, lsum0, 2);
    lsum1 += __shfl_xor_sync(0xFFFFFFFFu, lsum1, 1);
    lsum1 += __shfl_xor_sync(0xFFFFFFFFu, lsum1, 2);
    if (c == 0) {
        g_lp[q][r0] = lsum0;
        g_lp[q][r1] = lsum1;
    }

    // write partial numerators: group g -> feat base (g>>2)*64 + (g&3)*16
    float* np = g_np[q];
#pragma unroll
    for (int g = 0; g < 8; g++) {
#pragma unroll
        for (int b = 0; b < 2; b++) {
            const int ng = 2 * g + b;
            const int col = (g >> 2) * 64 + ((g & 3) * 2 + b) * 8 + c * 2;
            *(float2*)(np + (size_t)r0 * OUT_F + col) = make_float2(acc[ng][0], acc[ng][1]);
            *(float2*)(np + (size_t)r1 * OUT_F + col) = make_float2(acc[ng][2], acc[ng][3]);
        }
    }
}

// ---------------------------------------------------------------------------
// Kernel 4: combine 4 quarters, normalize
// ---------------------------------------------------------------------------
__global__ __launch_bounds__(256) void k_norm(float* __restrict__ out) {
    const int idx = blockIdx.x * 256 + threadIdx.x;  // float4 index
    const int i = idx >> 5;                          // row
    const float inv = 1.f / (((g_lp[0][i] + g_lp[1][i]) + (g_lp[2][i] + g_lp[3][i])));
    const float4 x0 = ((const float4*)g_np[0])[idx];
    const float4 x1 = ((const float4*)g_np[1])[idx];
    const float4 x2 = ((const float4*)g_np[2])[idx];
    const float4 x3 = ((const float4*)g_np[3])[idx];
    ((float4*)out)[idx] = make_float4(((x0.x + x1.x) + (x2.x + x3.x)) * inv,
                                      ((x0.y + x1.y) + (x2.y + x3.y)) * inv,
                                      ((x0.z + x1.z) + (x2.z + x3.z)) * inv,
                                      ((x0.w + x1.w) + (x2.w + x3.w)) * inv);
}

// ---------------------------------------------------------------------------
extern "C" void kernel_launch(void* const* d_in, const int* in_sizes, int n_in,
                              void* d_out, int out_size) {
    const float* h   = (const float*)d_in[0];
    const int*   adj = (const int*)d_in[1];
    const float* W   = (const float*)d_in[2];
    const float* a   = (const float*)d_in[3];
    float* out = (float*)d_out;

    k_proj<<<Nn / 32, 256>>>(h, W, a);
    k_pre<<<Nn / 256, 256>>>();
    k_attn<<<(Nn / 256) * SPLIT, 512>>>(adj);
    k_norm<<<Nn * OUT_F / 4 / 256, 256>>>(out);
}

// round 15
// speedup vs baseline: 1.0589x; 1.0589x over previous
#include <cuda_runtime.h>
#include <cuda_fp16.h>
#include <cstdint>

#define Nn 8192
#define IN_F 256
#define OUT_F 128
#define ALPHA 0.2f
#define SPLIT 8
#define JQ (Nn / SPLIT)    /* 1024 cols per CTA */
#define NIT (JQ / 16)      /* 64 k16 iterations */

// ---------------- scratch (device globals; no allocation allowed) ------------
__device__ float g_f1[Nn];
__device__ float g_f2[Nn];
__device__ float g_f2pmax[256];
__device__ __align__(16) float2 g_tab2[Nn];   // (exp(f2-fm), exp(a*(f2-fm)))
__device__ __align__(16) float2 g_rowc[Nn];   // (cp, cn)
// Wh in fp16, MMA-fragment-major, uint4-paired n-tiles (R12 layout, unchanged)
__device__ __align__(16) uint4 g_Bf[(Nn / 16) * 2 * 4 * 32];
__device__ float g_np[SPLIT][Nn * OUT_F];   // partial numerators per j-slice
__device__ float g_lp[SPLIT][Nn];           // partial row sums

// ---------------- helpers ----------------------------------------------------
__device__ __forceinline__ void mma_f16(float* d, const uint32_t* a, uint32_t b0, uint32_t b1) {
    asm volatile("mma.sync.aligned.m16n8k16.row.col.f32.f16.f16.f32 "
                 "{%0,%1,%2,%3},{%4,%5,%6,%7},{%8,%9},{%0,%1,%2,%3};"
                 : "+f"(d[0]), "+f"(d[1]), "+f"(d[2]), "+f"(d[3])
                 : "r"(a[0]), "r"(a[1]), "r"(a[2]), "r"(a[3]), "r"(b0), "r"(b1));
}

__device__ __forceinline__ uint32_t packh2(float hi, float lo) {
    uint32_t r;
    asm("cvt.rn.f16x2.f32 %0, %1, %2;" : "=r"(r) : "f"(hi), "f"(lo));
    return r;
}

// ---------------------------------------------------------------------------
// Kernel 1: Wh = h@W ; f1/f2, per-block f2 max, fragment-major fp16 Bf. (=R12)
// ---------------------------------------------------------------------------
__global__ __launch_bounds__(256) void k_proj(const float* __restrict__ h,
                                              const float* __restrict__ W,
                                              const float* __restrict__ a) {
    __shared__ float w_s[32 * 128];
    __shared__ float h_s[32 * 33];
    __shared__ float red[32];
    const int tid = threadIdx.x;
    const int i0 = blockIdx.x * 32;
    const int row = tid >> 3;
    const int c8 = tid & 7;
    float4 acc[4];
#pragma unroll
    for (int j4 = 0; j4 < 4; j4++) acc[j4] = make_float4(0.f, 0.f, 0.f, 0.f);

    for (int kc = 0; kc < IN_F; kc += 32) {
        __syncthreads();
        const float4* wsrc = (const float4*)(W + kc * OUT_F);
#pragma unroll
        for (int u = 0; u < 4; u++) ((float4*)w_s)[tid + u * 256] = wsrc[tid + u * 256];
        {
            float4 hv = *(const float4*)(h + (size_t)(i0 + row) * IN_F + kc + c8 * 4);
            h_s[row * 33 + c8 * 4 + 0] = hv.x;
            h_s[row * 33 + c8 * 4 + 1] = hv.y;
            h_s[row * 33 + c8 * 4 + 2] = hv.z;
            h_s[row * 33 + c8 * 4 + 3] = hv.w;
        }
        __syncthreads();
#pragma unroll
        for (int kk = 0; kk < 32; kk++) {
            const float hval = h_s[row * 33 + kk];
            const float4* wr = ((const float4*)w_s) + kk * 32 + c8;
#pragma unroll
            for (int j4 = 0; j4 < 4; j4++) {
                const float4 wv = wr[j4 * 8];
                acc[j4].x = fmaf(hval, wv.x, acc[j4].x);
                acc[j4].y = fmaf(hval, wv.y, acc[j4].y);
                acc[j4].z = fmaf(hval, wv.z, acc[j4].z);
                acc[j4].w = fmaf(hval, wv.w, acc[j4].w);
            }
        }
    }

    float s1 = 0.f, s2 = 0.f;
#pragma unroll
    for (int j4 = 0; j4 < 4; j4++) {
        const float4 a1v = *(const float4*)(a + c8 * 4 + j4 * 32);
        const float4 a2v = *(const float4*)(a + OUT_F + c8 * 4 + j4 * 32);
        s1 += acc[j4].x * a1v.x + acc[j4].y * a1v.y + acc[j4].z * a1v.z + acc[j4].w * a1v.w;
        s2 += acc[j4].x * a2v.x + acc[j4].y * a2v.y + acc[j4].z * a2v.z + acc[j4].w * a2v.w;
    }
#pragma unroll
    for (int o = 1; o < 8; o <<= 1) {
        s1 += __shfl_xor_sync(0xFFFFFFFFu, s1, o);
        s2 += __shfl_xor_sync(0xFFFFFFFFu, s2, o);
    }
    if (c8 == 0) { g_f1[i0 + row] = s1; g_f2[i0 + row] = s2; red[row] = s2; }
    __syncthreads();
    if (tid < 32) {
        float m = red[tid];
#pragma unroll
        for (int o = 16; o; o >>= 1) m = fmaxf(m, __shfl_xor_sync(0xFFFFFFFFu, m, o));
        if (tid == 0) g_f2pmax[blockIdx.x] = m;
    }

    // stage Wh into w_s, then fragment-major fp16 write
#pragma unroll
    for (int j4 = 0; j4 < 4; j4++)
        ((float4*)w_s)[row * 32 + c8 + j4 * 8] = acc[j4];
    __syncthreads();

    const int f = tid & 127;
    const int hb = tid >> 7;
    const int wn = f >> 6, nt = (f >> 3) & 7, nq = f & 7;
    uint32_t* bf32 = (uint32_t*)g_Bf;
#pragma unroll
    for (int q = 0; q < 8; q++) {
        const int jj = hb * 16 + 2 * q;
        const float v0 = w_s[jj * 128 + f];
        const float v1 = w_s[(jj + 1) * 128 + f];
        const uint32_t pk = packh2(v1, v0);
        const int jblk = (i0 + jj) >> 4;
        const int cc = (jj >> 2) & 3;
        const int v = jj & 3;
        const int widx = ((((jblk * 2 + wn) * 4 + (nt >> 1)) * 32) + nq * 4 + cc) * 4
                         + (nt & 1) * 2 + (v >> 1);
        bf32[widx] = pk;
    }
}

// ---------------------------------------------------------------------------
// Kernel 2: finish f2max reduction + build col/row tables. Grid 32 x 256.
// ---------------------------------------------------------------------------
__global__ __launch_bounds__(256) void k_pre() {
    __shared__ float red[256];
    const int t = threadIdx.x;
    red[t] = g_f2pmax[t];
    __syncthreads();
#pragma unroll
    for (int s = 128; s; s >>= 1) {
        if (t < s) red[t] = fmaxf(red[t], red[t + s]);
        __syncthreads();
    }
    const float fm = red[0];
    const int j = blockIdx.x * 256 + t;
    const float d = g_f2[j] - fm;
    g_tab2[j] = make_float2(expf(d), expf(ALPHA * d));
    const float f1 = g_f1[j];
    const float bound = f1 + fm;
    const float m = bound > 0.f ? bound : ALPHA * bound;
    g_rowc[j] = make_float2(expf(bound - m), expf(ALPHA * bound - m));
}

// ---------------------------------------------------------------------------
// Kernel 3: fused masked-softmax + fp16 HMMA PV GEMM. R12 inner loop verbatim;
// CTA shrunk to 128 threads (2 wm x 2 wn = 32 rows) and SPLIT=8 (1024 cols)
// -> 2048 CTAs: no wave quantization, ~6 CTAs/SM for latency hiding.
// ---------------------------------------------------------------------------
__global__ __launch_bounds__(128) void k_attn(const int* __restrict__ adj) {
    __shared__ float2 tab_s[JQ];   // 8 KB

    const int tid = threadIdx.x;
    const int wid = tid >> 5, lane = tid & 31;
    const int wm = wid >> 1, wn = wid & 1;
    const int nq = lane >> 2, c = lane & 3;
    const int rb = blockIdx.x >> 3, q = blockIdx.x & 7;
    const int i0 = rb * 32, jq = q * JQ;

    // stage the slice's exp table into smem (once)
    {
        const float4* src = (const float4*)(g_tab2 + jq);
        float4* dst = (float4*)tab_s;
#pragma unroll
        for (int u = 0; u < 4; u++) dst[tid + u * 128] = src[tid + u * 128];
    }

    const int r0 = i0 + wm * 16 + nq;
    const int r1 = r0 + 8;
    const float2 rc0 = g_rowc[r0];
    const float2 rc1 = g_rowc[r1];
    const float cp0 = rc0.x, cn0 = rc0.y;
    const float cp1 = rc1.x, cn1 = rc1.y;
    const int4* arow0 = (const int4*)(adj + (size_t)r0 * Nn);
    const int4* arow1 = (const int4*)(adj + (size_t)r1 * Nn);
    const int cibase = (jq >> 2) + c;
    const uint4* bfbase = g_Bf + ((size_t)(jq >> 4) * 2 + wn) * 128 + lane;

    float acc[8][4];
#pragma unroll
    for (int nt = 0; nt < 8; nt++)
#pragma unroll
        for (int u = 0; u < 4; u++) acc[nt][u] = 0.f;
    float lsum0 = 0.f, lsum1 = 0.f;

    // adj prefetch ring, distance 2
    int4 pa0[2], pa1[2];
    pa0[0] = arow0[cibase];     pa1[0] = arow1[cibase];
    pa0[1] = arow0[cibase + 4]; pa1[1] = arow1[cibase + 4];

    // B double buffer (copy-free, parity-indexed): 4 uint4 per iter
    uint4 bv[2][4];
#pragma unroll
    for (int ntp = 0; ntp < 4; ntp++) bv[0][ntp] = bfbase[ntp * 32];

    __syncthreads();   // tab_s ready (only barrier)

#pragma unroll 2
    for (int i = 0; i < NIT; i++) {
        const int jl = 16 * i + 4 * c;
        const int4 A0 = pa0[i & 1];
        const int4 A1 = pa1[i & 1];
        if (i + 2 < NIT) {
            pa0[i & 1] = arow0[cibase + 4 * (i + 2)];
            pa1[i & 1] = arow1[cibase + 4 * (i + 2)];
        }

        // prefetch next iteration's B into the other parity slot
        {
            const int inext = (i + 1 < NIT) ? i + 1 : i;
            const uint4* bq = bfbase + (size_t)inext * 256;
#pragma unroll
            for (int ntp = 0; ntp < 4; ntp++) bv[(i + 1) & 1][ntp] = bq[ntp * 32];
        }

        const float4 tA = *(const float4*)(tab_s + jl);      // cols j, j+1
        const float4 tB = *(const float4*)(tab_s + jl + 2);  // cols j+2, j+3

        float p00 = fmaxf(cp0 * tA.x, cn0 * tA.y);
        float p01 = fmaxf(cp0 * tA.z, cn0 * tA.w);
        float p02 = fmaxf(cp0 * tB.x, cn0 * tB.y);
        float p03 = fmaxf(cp0 * tB.z, cn0 * tB.w);
        float p10 = fmaxf(cp1 * tA.x, cn1 * tA.y);
        float p11 = fmaxf(cp1 * tA.z, cn1 * tA.w);
        float p12 = fmaxf(cp1 * tB.x, cn1 * tB.y);
        float p13 = fmaxf(cp1 * tB.z, cn1 * tB.w);
        p00 = (A0.x > 0) ? p00 : 0.f;
        p01 = (A0.y > 0) ? p01 : 0.f;
        p02 = (A0.z > 0) ? p02 : 0.f;
        p03 = (A0.w > 0) ? p03 : 0.f;
        p10 = (A1.x > 0) ? p10 : 0.f;
        p11 = (A1.y > 0) ? p11 : 0.f;
        p12 = (A1.z > 0) ? p12 : 0.f;
        p13 = (A1.w > 0) ? p13 : 0.f;
        lsum0 += (p00 + p01) + (p02 + p03);
        lsum1 += (p10 + p11) + (p12 + p13);

        uint32_t Af[4];
        Af[0] = packh2(p01, p00);   // row r0, k 2c/2c+1 (j 4c,4c+1)
        Af[1] = packh2(p11, p10);   // row r1
        Af[2] = packh2(p03, p02);   // row r0, k 2c+8/+9 (j 4c+2,4c+3)
        Af[3] = packh2(p13, p12);   // row r1

        const uint4* bcur = bv[i & 1];
#pragma unroll
        for (int ntp = 0; ntp < 4; ntp++) {
            mma_f16(acc[2 * ntp + 0], Af, bcur[ntp].x, bcur[ntp].y);
            mma_f16(acc[2 * ntp + 1], Af, bcur[ntp].z, bcur[ntp].w);
        }
    }

    // row-sum reduce across the 4 c-lanes of each quad
    lsum0 += __shfl_xor_sync(0xFFFFFFFFu, lsum0, 1);
    lsum0 += __shfl_xor_sync(0xFFFFFFFFu, lsum0, 2);
    lsum1 += __shfl_xor_sync(0xFFFFFFFFu, lsum1, 1);
    lsum1 += __shfl_xor_sync(0xFFFFFFFFu, lsum1, 2);
    if (wn == 0 && c == 0) {
        g_lp[q][r0] = lsum0;
        g_lp[q][r1] = lsum1;
    }

    // write partial numerators (d0/d1 row r0, d2/d3 row r1, cols 2c,2c+1)
    float* np = g_np[q];
#pragma unroll
    for (int nt = 0; nt < 8; nt++) {
        const int col = wn * 64 + nt * 8 + c * 2;
        *(float2*)(np + (size_t)r0 * OUT_F + col) = make_float2(acc[nt][0], acc[nt][1]);
        *(float2*)(np + (size_t)r1 * OUT_F + col) = make_float2(acc[nt][2], acc[nt][3]);
    }
}

// ---------------------------------------------------------------------------
// Kernel 4: combine 8 slices, normalize
// ---------------------------------------------------------------------------
__global__ __launch_bounds__(256) void k_norm(float* __restrict__ out) {
    const int idx = blockIdx.x * 256 + threadIdx.x;  // float4 index
    const int i = idx >> 5;                          // row
    float ls = 0.f;
#pragma unroll
    for (int s = 0; s < SPLIT; s++) ls += g_lp[s][i];
    const float inv = 1.f / ls;
    float4 acc = make_float4(0.f, 0.f, 0.f, 0.f);
#pragma unroll
    for (int s = 0; s < SPLIT; s++) {
        const float4 x = ((const float4*)g_np[s])[idx];
        acc.x += x.x; acc.y += x.y; acc.z += x.z; acc.w += x.w;
    }
    ((float4*)out)[idx] = make_float4(acc.x * inv, acc.y * inv, acc.z * inv, acc.w * inv);
}

// ---------------------------------------------------------------------------
extern "C" void kernel_launch(void* const* d_in, const int* in_sizes, int n_in,
                              void* d_out, int out_size) {
    const float* h   = (const float*)d_in[0];
    const int*   adj = (const int*)d_in[1];
    const float* W   = (const float*)d_in[2];
    const float* a   = (const float*)d_in[3];
    float* out = (float*)d_out;

    k_proj<<<Nn / 32, 256>>>(h, W, a);
    k_pre<<<Nn / 256, 256>>>();
    k_attn<<<(Nn / 32) * SPLIT, 128>>>(adj);
    k_norm<<<Nn * OUT_F / 4 / 256, 256>>>(out);
}

// round 16
// speedup vs baseline: 1.1737x; 1.1084x over previous
#include <cuda_runtime.h>
#include <cuda_fp16.h>
#include <cstdint>

#define Nn 8192
#define IN_F 256
#define OUT_F 128
#define ALPHA 0.2f
#define SPLIT 2
#define JHALF (Nn / SPLIT) /* 4096 */
#define NIT (JHALF / 16)   /* 256 k16 iterations */

// ---------------- scratch (device globals; no allocation allowed) ------------
__device__ float g_f1[Nn];
__device__ float g_f2[Nn];
__device__ float g_f2pmax[256];
__device__ __align__(16) float2 g_tab2[Nn];   // (exp(f2-fm), exp(a*(f2-fm)))
__device__ __align__(16) float2 g_rowc[Nn];   // (cp, cn)
// Wh in fp16, MMA-fragment-major, uint4-paired n-tiles:
//   uint4 index = (((jblk*2 + wn)*4 + ntp)*32 + lane)
//   .x/.y = b0/b1 of nt=2*ntp ; .z/.w = b0/b1 of nt=2*ntp+1
__device__ __align__(16) uint4 g_Bf[(Nn / 16) * 2 * 4 * 32];
__device__ float g_np0[Nn * OUT_F];   // partial numerators
__device__ float g_np1[Nn * OUT_F];
__device__ float g_lp0[Nn];           // partial row sums
__device__ float g_lp1[Nn];

// ---------------- helpers ----------------------------------------------------
__device__ __forceinline__ void mma_f16(float* d, const uint32_t* a, uint32_t b0, uint32_t b1) {
    asm volatile("mma.sync.aligned.m16n8k16.row.col.f32.f16.f16.f32 "
                 "{%0,%1,%2,%3},{%4,%5,%6,%7},{%8,%9},{%0,%1,%2,%3};"
                 : "+f"(d[0]), "+f"(d[1]), "+f"(d[2]), "+f"(d[3])
                 : "r"(a[0]), "r"(a[1]), "r"(a[2]), "r"(a[3]), "r"(b0), "r"(b1));
}

__device__ __forceinline__ uint32_t packh2(float hi, float lo) {
    uint32_t r;
    asm("cvt.rn.f16x2.f32 %0, %1, %2;" : "=r"(r) : "f"(hi), "f"(lo));
    return r;
}

// ---------------------------------------------------------------------------
// Kernel 1: Wh = h@W ; f1/f2, per-block f2 max, fragment-major fp16 Bf. (=R12)
// ---------------------------------------------------------------------------
__global__ __launch_bounds__(256) void k_proj(const float* __restrict__ h,
                                              const float* __restrict__ W,
                                              const float* __restrict__ a) {
    __shared__ float w_s[32 * 128];
    __shared__ float h_s[32 * 33];
    __shared__ float red[32];
    const int tid = threadIdx.x;
    const int i0 = blockIdx.x * 32;
    const int row = tid >> 3;
    const int c8 = tid & 7;
    float4 acc[4];
#pragma unroll
    for (int j4 = 0; j4 < 4; j4++) acc[j4] = make_float4(0.f, 0.f, 0.f, 0.f);

    for (int kc = 0; kc < IN_F; kc += 32) {
        __syncthreads();
        const float4* wsrc = (const float4*)(W + kc * OUT_F);
#pragma unroll
        for (int u = 0; u < 4; u++) ((float4*)w_s)[tid + u * 256] = wsrc[tid + u * 256];
        {
            float4 hv = *(const float4*)(h + (size_t)(i0 + row) * IN_F + kc + c8 * 4);
            h_s[row * 33 + c8 * 4 + 0] = hv.x;
            h_s[row * 33 + c8 * 4 + 1] = hv.y;
            h_s[row * 33 + c8 * 4 + 2] = hv.z;
            h_s[row * 33 + c8 * 4 + 3] = hv.w;
        }
        __syncthreads();
#pragma unroll
        for (int kk = 0; kk < 32; kk++) {
            const float hval = h_s[row * 33 + kk];
            const float4* wr = ((const float4*)w_s) + kk * 32 + c8;
#pragma unroll
            for (int j4 = 0; j4 < 4; j4++) {
                const float4 wv = wr[j4 * 8];
                acc[j4].x = fmaf(hval, wv.x, acc[j4].x);
                acc[j4].y = fmaf(hval, wv.y, acc[j4].y);
                acc[j4].z = fmaf(hval, wv.z, acc[j4].z);
                acc[j4].w = fmaf(hval, wv.w, acc[j4].w);
            }
        }
    }

    float s1 = 0.f, s2 = 0.f;
#pragma unroll
    for (int j4 = 0; j4 < 4; j4++) {
        const float4 a1v = *(const float4*)(a + c8 * 4 + j4 * 32);
        const float4 a2v = *(const float4*)(a + OUT_F + c8 * 4 + j4 * 32);
        s1 += acc[j4].x * a1v.x + acc[j4].y * a1v.y + acc[j4].z * a1v.z + acc[j4].w * a1v.w;
        s2 += acc[j4].x * a2v.x + acc[j4].y * a2v.y + acc[j4].z * a2v.z + acc[j4].w * a2v.w;
    }
#pragma unroll
    for (int o = 1; o < 8; o <<= 1) {
        s1 += __shfl_xor_sync(0xFFFFFFFFu, s1, o);
        s2 += __shfl_xor_sync(0xFFFFFFFFu, s2, o);
    }
    if (c8 == 0) { g_f1[i0 + row] = s1; g_f2[i0 + row] = s2; red[row] = s2; }
    __syncthreads();
    if (tid < 32) {
        float m = red[tid];
#pragma unroll
        for (int o = 16; o; o >>= 1) m = fmaxf(m, __shfl_xor_sync(0xFFFFFFFFu, m, o));
        if (tid == 0) g_f2pmax[blockIdx.x] = m;
    }

    // stage Wh into w_s, then fragment-major fp16 write (uint4-paired layout)
#pragma unroll
    for (int j4 = 0; j4 < 4; j4++)
        ((float4*)w_s)[row * 32 + c8 + j4 * 8] = acc[j4];
    __syncthreads();

    const int f = tid & 127;
    const int hb = tid >> 7;
    const int wn = f >> 6, nt = (f >> 3) & 7, nq = f & 7;
    uint32_t* bf32 = (uint32_t*)g_Bf;
#pragma unroll
    for (int q = 0; q < 8; q++) {
        const int jj = hb * 16 + 2 * q;
        const float v0 = w_s[jj * 128 + f];
        const float v1 = w_s[(jj + 1) * 128 + f];
        const uint32_t pk = packh2(v1, v0);
        const int jblk = (i0 + jj) >> 4;
        const int cc = (jj >> 2) & 3;
        const int v = jj & 3;
        const int widx = ((((jblk * 2 + wn) * 4 + (nt >> 1)) * 32) + nq * 4 + cc) * 4
                         + (nt & 1) * 2 + (v >> 1);
        bf32[widx] = pk;
    }
}

// ---------------------------------------------------------------------------
// Kernel 2: finish f2max reduction + build col/row tables. Grid 32 x 256.
// ---------------------------------------------------------------------------
__global__ __launch_bounds__(256) void k_pre() {
    __shared__ float red[256];
    const int t = threadIdx.x;
    red[t] = g_f2pmax[t];
    __syncthreads();
#pragma unroll
    for (int s = 128; s; s >>= 1) {
        if (t < s) red[t] = fmaxf(red[t], red[t + s]);
        __syncthreads();
    }
    const float fm = red[0];
    const int j = blockIdx.x * 256 + t;
    const float d = g_f2[j] - fm;
    g_tab2[j] = make_float2(expf(d), expf(ALPHA * d));
    const float f1 = g_f1[j];
    const float bound = f1 + fm;
    const float m = bound > 0.f ? bound : ALPHA * bound;
    // leaky_relu(s) = max(s, a*s)  =>  p = max(cp*e2p_j, cn*e2n_j)
    g_rowc[j] = make_float2(expf(bound - m), expf(ALPHA * bound - m));
}

// ---------------------------------------------------------------------------
// Kernel 3: fused masked-softmax + fp16 HMMA PV GEMM. Barrier-free main loop.
// R12 structure with ALL i+1 operands (adj/tab/B) prefetched into register
// rings before iteration i's compute — the pval chain never waits on memory.
// ---------------------------------------------------------------------------
__global__ __launch_bounds__(512, 1) void k_attn(const int* __restrict__ adj) {
    __shared__ float2 tab_s[JHALF];   // 32 KB

    const int tid = threadIdx.x;
    const int wid = tid >> 5, lane = tid & 31;
    const int wm = wid >> 1, wn = wid & 1;
    const int nq = lane >> 2, c = lane & 3;
    const int rb = blockIdx.x >> 1, half = blockIdx.x & 1;
    const int i0 = rb * 128, jh = half * JHALF;

    // stage the half's exp table into smem (once)
    {
        const float4* src = (const float4*)(g_tab2 + jh);
        float4* dst = (float4*)tab_s;
#pragma unroll
        for (int q = 0; q < 4; q++) dst[tid + q * 512] = src[tid + q * 512];
    }

    const int r0 = i0 + wm * 16 + nq;
    const int r1 = r0 + 8;
    const float2 rc0 = g_rowc[r0];
    const float2 rc1 = g_rowc[r1];
    const float cp0 = rc0.x, cn0 = rc0.y;
    const float cp1 = rc1.x, cn1 = rc1.y;
    const int4* arow0 = (const int4*)(adj + (size_t)r0 * Nn);
    const int4* arow1 = (const int4*)(adj + (size_t)r1 * Nn);
    const int cibase = (jh >> 2) + c;
    const uint4* bfbase = g_Bf + ((size_t)(jh >> 4) * 2 + wn) * 128 + lane;

    float acc[8][4];
#pragma unroll
    for (int nt = 0; nt < 8; nt++)
#pragma unroll
        for (int q = 0; q < 4; q++) acc[nt][q] = 0.f;
    float lsum0 = 0.f, lsum1 = 0.f;

    // adj prefetch ring, distance 2
    int4 pa0[2], pa1[2];
    pa0[0] = arow0[cibase];     pa1[0] = arow1[cibase];
    pa0[1] = arow0[cibase + 4]; pa1[1] = arow1[cibase + 4];

    // B double buffer (copy-free, parity-indexed): 4 uint4 per iter
    uint4 bv[2][4];
#pragma unroll
    for (int ntp = 0; ntp < 4; ntp++) bv[0][ntp] = bfbase[ntp * 32];

    __syncthreads();   // tab_s ready (only barrier)

    // tab prefetch ring, distance 1 (i=0 values)
    float4 tAr = *(const float4*)(tab_s + 4 * c);
    float4 tBr = *(const float4*)(tab_s + 4 * c + 2);

#pragma unroll 2
    for (int i = 0; i < NIT; i++) {
        const int4 A0 = pa0[i & 1];
        const int4 A1 = pa1[i & 1];
        const float4 tA = tAr;   // cols j, j+1
        const float4 tB = tBr;   // cols j+2, j+3

        // ---- prefetch everything for upcoming iterations FIRST ----
        if (i + 2 < NIT) {
            pa0[i & 1] = arow0[cibase + 4 * (i + 2)];
            pa1[i & 1] = arow1[cibase + 4 * (i + 2)];
        }
        {
            const int inext = (i + 1 < NIT) ? i + 1 : i;
            const int jln = 16 * inext + 4 * c;
            tAr = *(const float4*)(tab_s + jln);
            tBr = *(const float4*)(tab_s + jln + 2);
            const uint4* bq = bfbase + (size_t)inext * 256;
#pragma unroll
            for (int ntp = 0; ntp < 4; ntp++) bv[(i + 1) & 1][ntp] = bq[ntp * 32];
        }

        // ---- pval chain (no memory waits) ----
        float p00 = fmaxf(cp0 * tA.x, cn0 * tA.y);
        float p01 = fmaxf(cp0 * tA.z, cn0 * tA.w);
        float p02 = fmaxf(cp0 * tB.x, cn0 * tB.y);
        float p03 = fmaxf(cp0 * tB.z, cn0 * tB.w);
        float p10 = fmaxf(cp1 * tA.x, cn1 * tA.y);
        float p11 = fmaxf(cp1 * tA.z, cn1 * tA.w);
        float p12 = fmaxf(cp1 * tB.x, cn1 * tB.y);
        float p13 = fmaxf(cp1 * tB.z, cn1 * tB.w);
        p00 = (A0.x > 0) ? p00 : 0.f;
        p01 = (A0.y > 0) ? p01 : 0.f;
        p02 = (A0.z > 0) ? p02 : 0.f;
        p03 = (A0.w > 0) ? p03 : 0.f;
        p10 = (A1.x > 0) ? p10 : 0.f;
        p11 = (A1.y > 0) ? p11 : 0.f;
        p12 = (A1.z > 0) ? p12 : 0.f;
        p13 = (A1.w > 0) ? p13 : 0.f;

        uint32_t Af[4];
        Af[0] = packh2(p01, p00);   // row r0, k 2c/2c+1 (j 4c,4c+1)
        Af[1] = packh2(p11, p10);   // row r1
        Af[2] = packh2(p03, p02);   // row r0, k 2c+8/+9 (j 4c+2,4c+3)
        Af[3] = packh2(p13, p12);   // row r1

        const uint4* bcur = bv[i & 1];
#pragma unroll
        for (int ntp = 0; ntp < 4; ntp++) {
            mma_f16(acc[2 * ntp + 0], Af, bcur[ntp].x, bcur[ntp].y);
            mma_f16(acc[2 * ntp + 1], Af, bcur[ntp].z, bcur[ntp].w);
        }

        // lsum off the critical path (after MMAs)
        lsum0 += (p00 + p01) + (p02 + p03);
        lsum1 += (p10 + p11) + (p12 + p13);
    }

    // row-sum reduce across the 4 c-lanes of each quad
    lsum0 += __shfl_xor_sync(0xFFFFFFFFu, lsum0, 1);
    lsum0 += __shfl_xor_sync(0xFFFFFFFFu, lsum0, 2);
    lsum1 += __shfl_xor_sync(0xFFFFFFFFu, lsum1, 1);
    lsum1 += __shfl_xor_sync(0xFFFFFFFFu, lsum1, 2);
    if (wn == 0 && c == 0) {
        float* lp = half ? g_lp1 : g_lp0;
        lp[r0] = lsum0;
        lp[r1] = lsum1;
    }

    // write partial numerators (d0/d1 row r0, d2/d3 row r1, cols 2c,2c+1)
    float* np = half ? g_np1 : g_np0;
#pragma unroll
    for (int nt = 0; nt < 8; nt++) {
        const int col = wn * 64 + nt * 8 + c * 2;
        *(float2*)(np + (size_t)r0 * OUT_F + col) = make_float2(acc[nt][0], acc[nt][1]);
        *(float2*)(np + (size_t)r1 * OUT_F + col) = make_float2(acc[nt][2], acc[nt][3]);
    }
}

// ---------------------------------------------------------------------------
// Kernel 4: combine halves, normalize
// ---------------------------------------------------------------------------
__global__ __launch_bounds__(256) void k_norm(float* __restrict__ out) {
    const int idx = blockIdx.x * 256 + threadIdx.x;  // float4 index
    const int i = idx >> 5;                          // row
    const float inv = 1.f / (g_lp0[i] + g_lp1[i]);
    const float4 x = ((const float4*)g_np0)[idx];
    const float4 y = ((const float4*)g_np1)[idx];
    ((float4*)out)[idx] = make_float4((x.x + y.x) * inv, (x.y + y.y) * inv,
                                      (x.z + y.z) * inv, (x.w + y.w) * inv);
}

// ---------------------------------------------------------------------------
extern "C" void kernel_launch(void* const* d_in, const int* in_sizes, int n_in,
                              void* d_out, int out_size) {
    const float* h   = (const float*)d_in[0];
    const int*   adj = (const int*)d_in[1];
    const float* W   = (const float*)d_in[2];
    const float* a   = (const float*)d_in[3];
    float* out = (float*)d_out;

    k_proj<<<Nn / 32, 256>>>(h, W, a);
    k_pre<<<Nn / 256, 256>>>();
    k_attn<<<(Nn / 128) * SPLIT, 512>>>(adj);
    k_norm<<<Nn * OUT_F / 4 / 256, 256>>>(out);
}